// round 10
// baseline (speedup 1.0000x reference)
#include <cuda_runtime.h>
#include <cuda_bf16.h>
#include <cstddef>

// B=4, S=2048, D=1024, I=1024. Keys are broadcast-identical -> softmax == 1/S
// exactly -> out[b,s,:] = ((mean_s x[b,s,:]) @ Wv) @ Wo, independent of s.
//
// R10 = R9 staged batch-pair pipeline with the correctness fix: g_yp gathers
// in writep use PLAIN coherent loads (R9 used __ldg — non-coherent path —
// on same-launch cross-block writes, which served stale lines).
// 128 blocks x 1024 threads, 4 grid barriers; colsum(pair1) inside barrier-0's
// arrive/wait window; write(p0) store drain overlaps gemv2(p1).

#define SEQ   2048
#define DIM   1024
#define NBLK  128
#define NTHR  1024
#define NBAR  4

__device__ float g_part[4 * 64 * DIM];   // 1 MB colsum partials (64 sp/batch)
__device__ float g_tp  [4 * 16 * DIM];   // gemv1 partials (16 d-slices)
__device__ float g_yp  [4 * 16 * DIM];   // gemv2 partials

__device__ unsigned g_bar_cnt[NBAR];
__device__ unsigned g_bar_gen[NBAR];

__device__ __forceinline__ void bar_arrive(int i, unsigned& gen) {
    __syncthreads();
    if (threadIdx.x == 0) {
        __threadfence();
        gen = *(volatile unsigned*)&g_bar_gen[i];
        unsigned old = atomicAdd(&g_bar_cnt[i], 1u);
        if (old == NBLK - 1) {
            g_bar_cnt[i] = 0;
            __threadfence();
            atomicAdd(&g_bar_gen[i], 1u);
        }
    }
}
__device__ __forceinline__ void bar_wait(int i, unsigned gen) {
    if (threadIdx.x == 0) {
        while (*(volatile unsigned*)&g_bar_gen[i] == gen) { }
        __threadfence();
    }
    __syncthreads();
}

// ---- colsum for one batch pair: 128 blocks x 32 rows ---------------------
__device__ __forceinline__ void colsum(const float* __restrict__ x, int pair) {
    const int tid = threadIdx.x, blk = blockIdx.x;
    const int bb = blk >> 6, sp = blk & 63;
    const int b  = pair * 2 + bb;
    const int r4 = tid & 3, c = tid >> 2;

    const float4* xp = reinterpret_cast<const float4*>(x)
                     + (size_t)(b * SEQ + sp * 32 + r4) * 256 + c;
    float4 a0 = make_float4(0.f, 0.f, 0.f, 0.f), a1 = a0;
#pragma unroll
    for (int k = 0; k < 4; ++k) {
        float4 v0 = xp[(size_t)(2 * k)     * 1024];
        float4 v1 = xp[(size_t)(2 * k + 1) * 1024];
        a0.x += v0.x; a0.y += v0.y; a0.z += v0.z; a0.w += v0.w;
        a1.x += v1.x; a1.y += v1.y; a1.z += v1.z; a1.w += v1.w;
    }
    float4 s = make_float4(a0.x + a1.x, a0.y + a1.y, a0.z + a1.z, a0.w + a1.w);
#pragma unroll
    for (int m = 1; m <= 2; m <<= 1) {
        s.x += __shfl_xor_sync(0xffffffffu, s.x, m);
        s.y += __shfl_xor_sync(0xffffffffu, s.y, m);
        s.z += __shfl_xor_sync(0xffffffffu, s.z, m);
        s.w += __shfl_xor_sync(0xffffffffu, s.w, m);
    }
    if (r4 == 0)
        reinterpret_cast<float4*>(g_part)[(b * 64 + sp) * 256 + c] = s;
}

// ---- gemv1: t_partial[b][ds][i] for both batches of a pair ---------------
__device__ __forceinline__ void gemv1(const float* __restrict__ Wv, int pair,
                                      float* s_g, float* s_xs) {
    const int tid = threadIdx.x, blk = blockIdx.x;
    const int ds = blk >> 3, ic = blk & 7;
    const int d0 = ds * 64;
    const int dg = tid >> 7, il = tid & 127;
    const int i  = ic * 128 + il;

    float w[8];
#pragma unroll
    for (int dd = 0; dd < 8; ++dd)
        w[dd] = __ldg(&Wv[(size_t)(d0 + dg * 8 + dd) * DIM + i]);  // immutable

    {   // gather: 8-way split-parallel over 64 sp-partials (plain loads)
        const int q = tid >> 7, rem = tid & 127;
        const int bb = rem >> 6, dm = rem & 63;
        const int b  = pair * 2 + bb;
        float s = 0.f;
#pragma unroll
        for (int p = 0; p < 8; ++p)
            s += g_part[(b * 64 + q * 8 + p) * DIM + d0 + dm];
        s_g[q * 128 + rem] = s;
    }
    __syncthreads();
    if (tid < 128) {
        float s = 0.f;
#pragma unroll
        for (int q = 0; q < 8; ++q) s += s_g[q * 128 + tid];
        s_xs[tid] = s * (1.0f / (float)SEQ);
    }
    __syncthreads();

    float a0 = 0.f, a1 = 0.f;
#pragma unroll
    for (int dd = 0; dd < 8; ++dd) {
        const int dl = dg * 8 + dd;
        a0 += s_xs[dl]      * w[dd];
        a1 += s_xs[64 + dl] * w[dd];
    }
    s_g[(0 * 8 + dg) * 128 + il] = a0;
    s_g[(1 * 8 + dg) * 128 + il] = a1;
    __syncthreads();
    if (tid < 256) {
        const int bb = tid >> 7, il2 = tid & 127;
        float s = 0.f;
#pragma unroll
        for (int g = 0; g < 8; ++g) s += s_g[(bb * 8 + g) * 128 + il2];
        g_tp[((pair * 2 + bb) * 16 + ds) * DIM + ic * 128 + il2] = s;
    }
    __syncthreads();
}

// ---- gemv2: y_partial[b][is][o] for both batches of a pair ---------------
__device__ __forceinline__ void gemv2(const float* __restrict__ Wo, int pair,
                                      float* s_g, float* s_xs) {
    const int tid = threadIdx.x, blk = blockIdx.x;
    const int is = blk >> 3, ic = blk & 7;
    const int i0 = is * 64;
    const int ig = tid >> 7, ol = tid & 127;
    const int o  = ic * 128 + ol;

    float w[8];
#pragma unroll
    for (int ii = 0; ii < 8; ++ii)
        w[ii] = __ldg(&Wo[(size_t)(i0 + ig * 8 + ii) * DIM + o]);  // immutable

    {   // gather: 8-way split over 16 ds-partials (plain loads)
        const int q = tid >> 7, rem = tid & 127;
        const int bb = rem >> 6, im = rem & 63;
        const int b  = pair * 2 + bb;
        float s = g_tp[(b * 16 + q * 2 + 0) * DIM + i0 + im]
                + g_tp[(b * 16 + q * 2 + 1) * DIM + i0 + im];
        s_g[q * 128 + rem] = s;
    }
    __syncthreads();
    if (tid < 128) {
        float s = 0.f;
#pragma unroll
        for (int q = 0; q < 8; ++q) s += s_g[q * 128 + tid];
        s_xs[tid] = s;
    }
    __syncthreads();

    float a0 = 0.f, a1 = 0.f;
#pragma unroll
    for (int ii = 0; ii < 8; ++ii) {
        const int il = ig * 8 + ii;
        a0 += s_xs[il]      * w[ii];
        a1 += s_xs[64 + il] * w[ii];
    }
    s_g[(0 * 8 + ig) * 128 + ol] = a0;
    s_g[(1 * 8 + ig) * 128 + ol] = a1;
    __syncthreads();
    if (tid < 256) {
        const int bb = tid >> 7, ol2 = tid & 127;
        float s = 0.f;
#pragma unroll
        for (int g = 0; g < 8; ++g) s += s_g[(bb * 8 + g) * 128 + ol2];
        g_yp[((pair * 2 + bb) * 16 + is) * DIM + ic * 128 + ol2] = s;
    }
    __syncthreads();
}

// ---- write: finalize y and broadcast 32 rows per block -------------------
// PLAIN coherent loads of g_yp (same-launch cross-block data). Redundant x4
// across r4 -> L1 broadcast. 8 streaming float4 stores. No smem, no sync.
__device__ __forceinline__ void writep(float* __restrict__ out, int pair) {
    const int tid = threadIdx.x, blk = blockIdx.x;
    const int bb = blk >> 6, sb = blk & 63;
    const int b  = pair * 2 + bb;
    const int r4 = tid & 3, c = tid >> 2;

    const float4* yp4 = reinterpret_cast<const float4*>(g_yp);
    float4 v0 = make_float4(0.f, 0.f, 0.f, 0.f), v1 = v0;
#pragma unroll
    for (int p = 0; p < 8; ++p) {
        float4 t0 = yp4[(b * 16 + 2 * p)     * 256 + c];
        float4 t1 = yp4[(b * 16 + 2 * p + 1) * 256 + c];
        v0.x += t0.x; v0.y += t0.y; v0.z += t0.z; v0.w += t0.w;
        v1.x += t1.x; v1.y += t1.y; v1.z += t1.z; v1.w += t1.w;
    }
    const float4 v = make_float4(v0.x + v1.x, v0.y + v1.y,
                                 v0.z + v1.z, v0.w + v1.w);
    float4* o4 = reinterpret_cast<float4*>(out)
               + (size_t)(b * SEQ + sb * 32 + r4) * 256 + c;
#pragma unroll
    for (int j = 0; j < 8; ++j)
        __stcs(&o4[(size_t)j * 1024], v);
}

__global__ void __launch_bounds__(NTHR, 1)
fusion_staged(const float* __restrict__ x,
              const float* __restrict__ Wv,
              const float* __restrict__ Wo,
              float* __restrict__ out) {
    __shared__ __align__(16) float s_g[2048];   // 8 KB
    __shared__ float s_xs[128];
    unsigned g0 = 0, g1 = 0, g2 = 0, g3 = 0;

    colsum(x, 0);                 // 16 MB read (pair 0)
    bar_arrive(0, g0);
    colsum(x, 1);                 // 16 MB read (pair 1) inside bar0 window
    bar_wait(0, g0);

    gemv1(Wv, 0, s_g, s_xs);      // overlaps stragglers' colsum(1)
    bar_arrive(1, g1);
    bar_wait(1, g1);

    gemv2(Wo, 0, s_g, s_xs);      // both tiny gemvs back-to-back
    gemv1(Wv, 1, s_g, s_xs);
    bar_arrive(2, g2);
    bar_wait(2, g2);

    writep(out, 0);               // 16 MB store issue...
    gemv2(Wo, 1, s_g, s_xs);      // ...drains during gemv2(p1)
    bar_arrive(3, g3);
    bar_wait(3, g3);

    writep(out, 1);               // 16 MB store
}

// Inputs: 0=inputs_embeds [B,S,D] f32, 1=structure_features, 2=Wq, 3=Wk,
// 4=Wv [D,I] f32, 5=Wo [I,D] f32, 6=num_heads. Only x, Wv, Wo matter.
extern "C" void kernel_launch(void* const* d_in, const int* in_sizes, int n_in,
                              void* d_out, int out_size) {
    (void)in_sizes; (void)n_in; (void)out_size;
    const float* x  = (const float*)d_in[0];
    const float* Wv = (const float*)d_in[4];
    const float* Wo = (const float*)d_in[5];
    fusion_staged<<<NBLK, NTHR>>>(x, Wv, Wo, (float*)d_out);
}

// round 11
// speedup vs baseline: 1.3908x; 1.3908x over previous
#include <cuda_runtime.h>
#include <cuda_bf16.h>
#include <cstddef>

// B=4, S=2048, D=1024, I=1024. Keys are broadcast-identical -> softmax == 1/S
// exactly -> out[b,s,:] = ((mean_s x[b,s,:]) @ Wv) @ Wo, independent of s.
//
// R11 = R8 skeleton (128 blocks x 1024 threads, 4 phases / 3 split barriers)
// with inverted cache policy for steady-state L2 residency across graph
// replays: x is read with __ldcs (evict-first, touched once per replay) and
// the output is stored PLAIN (write-back, evict-normal) so its 32 MB of
// lines stay L2-resident and are simply overwritten next replay (no DRAM
// write-back). Working set 73.5 MB < 126 MB L2. P4 is smem/sync-free.

#define SEQ   2048
#define DIM   1024
#define NBLK  128
#define NTHR  1024
#define SPB   32
#define NBAR  3

__device__ float g_part[4 * SPB * DIM];  // 512 KB colsum partials
__device__ float g_tp  [4 * 16 * DIM];   // gemv1 partials
__device__ float g_yp  [4 * 16 * DIM];   // gemv2 partials

__device__ unsigned g_bar_cnt[NBAR];
__device__ unsigned g_bar_gen[NBAR];

__device__ __forceinline__ void bar_arrive(int i, unsigned& gen) {
    __syncthreads();
    if (threadIdx.x == 0) {
        __threadfence();
        gen = *(volatile unsigned*)&g_bar_gen[i];
        unsigned old = atomicAdd(&g_bar_cnt[i], 1u);
        if (old == NBLK - 1) {
            g_bar_cnt[i] = 0;
            __threadfence();
            atomicAdd(&g_bar_gen[i], 1u);
        }
    }
}
__device__ __forceinline__ void bar_wait(int i, unsigned gen) {
    if (threadIdx.x == 0) {
        while (*(volatile unsigned*)&g_bar_gen[i] == gen) { }
        __threadfence();
    }
    __syncthreads();
}

__global__ void __launch_bounds__(NTHR, 1)
fusion_persistent(const float* __restrict__ x,
                  const float* __restrict__ Wv,
                  const float* __restrict__ Wo,
                  float* __restrict__ out) {
    const int blk = blockIdx.x;
    const int tid = threadIdx.x;
    unsigned gen0 = 0, gen1 = 0, gen2 = 0;

    __shared__ __align__(16) float s_red[4096];  // 16 KB (P1/P2/P3)
    __shared__ float s_xs[256];

    // ---------------- Phase 1: column-sum partials of x --------------------
    // __ldcs: x is single-use per replay; evict-first keeps the output +
    // weights resident in L2 across replays.
    {
        const int b  = blk >> 5;
        const int sp = blk & 31;
        const int r4 = tid >> 8;
        const int c  = tid & 255;
        const float4* xp = reinterpret_cast<const float4*>(x)
                         + (size_t)(b * SEQ + sp * 64 + r4) * 256 + c;
        float4 a0 = make_float4(0.f,0.f,0.f,0.f), a1 = a0, a2 = a0, a3 = a0;
#pragma unroll
        for (int k = 0; k < 4; ++k) {
            float4 v0 = __ldcs(&xp[(size_t)(4 * k + 0) * 1024]);
            float4 v1 = __ldcs(&xp[(size_t)(4 * k + 1) * 1024]);
            float4 v2 = __ldcs(&xp[(size_t)(4 * k + 2) * 1024]);
            float4 v3 = __ldcs(&xp[(size_t)(4 * k + 3) * 1024]);
            a0.x += v0.x; a0.y += v0.y; a0.z += v0.z; a0.w += v0.w;
            a1.x += v1.x; a1.y += v1.y; a1.z += v1.z; a1.w += v1.w;
            a2.x += v2.x; a2.y += v2.y; a2.z += v2.z; a2.w += v2.w;
            a3.x += v3.x; a3.y += v3.y; a3.z += v3.z; a3.w += v3.w;
        }
        float4 acc = make_float4(a0.x + a1.x + a2.x + a3.x,
                                 a0.y + a1.y + a2.y + a3.y,
                                 a0.z + a1.z + a2.z + a3.z,
                                 a0.w + a1.w + a2.w + a3.w);
        float4* sb4 = reinterpret_cast<float4*>(s_red);
        sb4[tid] = acc;
        __syncthreads();
        if (tid < 256) {
            float4 a = sb4[tid], b1 = sb4[tid + 256],
                   c1 = sb4[tid + 512], d1 = sb4[tid + 768];
            float4 r = make_float4(a.x + b1.x + c1.x + d1.x,
                                   a.y + b1.y + c1.y + d1.y,
                                   a.z + b1.z + c1.z + d1.z,
                                   a.w + b1.w + c1.w + d1.w);
            reinterpret_cast<float4*>(g_part)[(b * SPB + sp) * 256 + tid] = r;
        }
    }
    bar_arrive(0, gen0);

    // ---------------- Phase 2: t = xbar @ Wv ------------------------------
    const int ds = blk >> 3, ic = blk & 7;
    const int d0 = ds * 64;
    const int dg = tid >> 7, il = tid & 127;
    const int i2 = ic * 128 + il;

    float w[8];
#pragma unroll
    for (int dd = 0; dd < 8; ++dd)   // prefetch Wv in the wait window
        w[dd] = __ldg(&Wv[(size_t)(d0 + dg * 8 + dd) * DIM + i2]);

    bar_wait(0, gen0);
    {
        {
            const int q  = tid >> 8;
            const int rem = tid & 255;
            const int bb = rem >> 6, dm = rem & 63;
            float s = 0.f;
#pragma unroll
            for (int p = 0; p < 8; ++p)
                s += g_part[(bb * SPB + q * 8 + p) * DIM + d0 + dm];
            s_red[q * 256 + rem] = s;
        }
        __syncthreads();
        if (tid < 256)
            s_xs[tid] = (s_red[tid] + s_red[256 + tid] +
                         s_red[512 + tid] + s_red[768 + tid]) * (1.0f / (float)SEQ);
        __syncthreads();

        float a0 = 0.f, a1 = 0.f, a2 = 0.f, a3 = 0.f;
#pragma unroll
        for (int dd = 0; dd < 8; ++dd) {
            const int dl = dg * 8 + dd;
            a0 += s_xs[dl]       * w[dd];
            a1 += s_xs[64 + dl]  * w[dd];
            a2 += s_xs[128 + dl] * w[dd];
            a3 += s_xs[192 + dl] * w[dd];
        }
        __syncthreads();
        s_red[(0 * 8 + dg) * 128 + il] = a0;
        s_red[(1 * 8 + dg) * 128 + il] = a1;
        s_red[(2 * 8 + dg) * 128 + il] = a2;
        s_red[(3 * 8 + dg) * 128 + il] = a3;
        __syncthreads();
        if (tid < 512) {
            const int bb = tid >> 7, il2 = tid & 127;
            float s = 0.f;
#pragma unroll
            for (int g = 0; g < 8; ++g) s += s_red[(bb * 8 + g) * 128 + il2];
            g_tp[(bb * 16 + ds) * DIM + ic * 128 + il2] = s;
        }
    }
    bar_arrive(1, gen1);

    // ---------------- Phase 3: y = t @ Wo ---------------------------------
#pragma unroll
    for (int ii = 0; ii < 8; ++ii)   // prefetch Wo in the wait window
        w[ii] = __ldg(&Wo[(size_t)(d0 + dg * 8 + ii) * DIM + i2]);

    bar_wait(1, gen1);
    {
        {
            const int q  = tid >> 8;
            const int rem = tid & 255;
            const int bb = rem >> 6, im = rem & 63;
            float s = 0.f;
#pragma unroll
            for (int p = 0; p < 4; ++p)
                s += g_tp[(bb * 16 + q * 4 + p) * DIM + d0 + im];
            s_red[q * 256 + rem] = s;
        }
        __syncthreads();
        if (tid < 256)
            s_xs[tid] = s_red[tid] + s_red[256 + tid] +
                        s_red[512 + tid] + s_red[768 + tid];
        __syncthreads();

        float a0 = 0.f, a1 = 0.f, a2 = 0.f, a3 = 0.f;
#pragma unroll
        for (int ii = 0; ii < 8; ++ii) {
            const int il3 = dg * 8 + ii;
            a0 += s_xs[il3]       * w[ii];
            a1 += s_xs[64 + il3]  * w[ii];
            a2 += s_xs[128 + il3] * w[ii];
            a3 += s_xs[192 + il3] * w[ii];
        }
        __syncthreads();
        s_red[(0 * 8 + dg) * 128 + il] = a0;
        s_red[(1 * 8 + dg) * 128 + il] = a1;
        s_red[(2 * 8 + dg) * 128 + il] = a2;
        s_red[(3 * 8 + dg) * 128 + il] = a3;
        __syncthreads();
        if (tid < 512) {
            const int bb = tid >> 7, ol2 = tid & 127;
            float s = 0.f;
#pragma unroll
            for (int g = 0; g < 8; ++g) s += s_red[(bb * 8 + g) * 128 + ol2];
            g_yp[(bb * 16 + ds) * DIM + ic * 128 + ol2] = s;
        }
    }
    bar_arrive(2, gen2);
    bar_wait(2, gen2);

    // ---------------- Phase 4: finalize + broadcast (smem/sync-free) -------
    // Per-thread float4 finalize of its own column (x4 redundant across r4 ->
    // L1 broadcast), then 16 PLAIN stores: write-back, evict-normal, so the
    // output stays L2-resident between replays (overwritten, never drained).
    {
        const int b  = blk >> 5;
        const int sb = blk & 31;
        const int r4 = tid >> 8, c = tid & 255;

        const float4* yp4 = reinterpret_cast<const float4*>(g_yp);
        float4 v = make_float4(0.f, 0.f, 0.f, 0.f);
#pragma unroll
        for (int p = 0; p < 16; ++p) {
            float4 t = yp4[(b * 16 + p) * 256 + c];
            v.x += t.x; v.y += t.y; v.z += t.z; v.w += t.w;
        }
        float4* o4 = reinterpret_cast<float4*>(out)
                   + (size_t)(b * SEQ + sb * 64 + r4) * 256 + c;
#pragma unroll
        for (int r = 0; r < 16; ++r)
            o4[(size_t)r * 1024] = v;
    }
}

// Inputs: 0=inputs_embeds [B,S,D] f32, 1=structure_features, 2=Wq, 3=Wk,
// 4=Wv [D,I] f32, 5=Wo [I,D] f32, 6=num_heads. Only x, Wv, Wo matter.
extern "C" void kernel_launch(void* const* d_in, const int* in_sizes, int n_in,
                              void* d_out, int out_size) {
    (void)in_sizes; (void)n_in; (void)out_size;
    const float* x  = (const float*)d_in[0];
    const float* Wv = (const float*)d_in[4];
    const float* Wo = (const float*)d_in[5];
    fusion_persistent<<<NBLK, NTHR>>>(x, Wv, Wo, (float*)d_out);
}